// round 11
// baseline (speedup 1.0000x reference)
#include <cuda_runtime.h>
#include <math.h>

#define B_TOT 4096
#define IC 64
#define OC 16
#define DD 64

typedef unsigned long long ull;

static __device__ float g_tempF[B_TOT * IC * DD];   // [b][i][h]
static __device__ float g_xhat [B_TOT * OC * DD];   // [b][m][f]
static __device__ float g_y    [B_TOT * DD];        // [b][h]
static __device__ float g_fa   [B_TOT * IC];
static __device__ float g_WG12 [OC * DD * DD];      // [m][d][f]
static __device__ float g_bsum [IC * OC];
static __device__ float g_bI   [IC];
static __device__ float g_c0   [IC];

// ---- packed f32x2 helpers (Blackwell) ----
__device__ __forceinline__ void fma2(ull& d, ull a, ull b) {
    asm("fma.rn.f32x2 %0, %1, %2, %0;" : "+l"(d) : "l"(a), "l"(b));
}
__device__ __forceinline__ ull mul2(ull a, ull b) {
    ull r; asm("mul.rn.f32x2 %0, %1, %2;" : "=l"(r) : "l"(a), "l"(b)); return r;
}
__device__ __forceinline__ ull bcast2(float x) {
    ull r; asm("mov.b64 %0, {%1, %1};" : "=l"(r) : "r"(__float_as_uint(x))); return r;
}
__device__ __forceinline__ float2 unpk(ull v) {
    float2 f; asm("mov.b64 {%0, %1}, %2;" : "=f"(f.x), "=f"(f.y) : "l"(v)); return f;
}

// -------------------- k_wg12p: blocks 0-15 = W_G12[m]; block 16 = beta prep
__global__ void k_wg12p(const float* __restrict__ W_G1, const float* __restrict__ W_G2,
                        const float* __restrict__ bu, const float* __restrict__ bg) {
    if (blockIdx.x == 16) {
        int i = threadIdx.x;
        if (i < 64) {
            float bi = 0.f, cs = 0.f;
            #pragma unroll
            for (int m = 0; m < OC; m++) {
                float u = bu[i * OC + m], g = bg[i * OC + m];
                float s = u + g;
                g_bsum[i * OC + m] = s;
                bi += g; cs += s;
            }
            g_bI[i] = bi;
            g_c0[i] = cs * (1.f / OC) - bi;
        }
        return;
    }
    __shared__ float wg1[64 * 65];
    __shared__ float wg2[64 * 64];
    int m = blockIdx.x, t = threadIdx.x;
    for (int idx = t; idx < 4096; idx += 256) {
        int d = idx >> 6, h = idx & 63;
        wg1[d * 65 + h] = W_G1[idx];
        wg2[idx]        = W_G2[m * 4096 + idx];
    }
    __syncthreads();
    int d = t >> 2, i0 = (t & 3) * 16;
    float acc[16];
    #pragma unroll
    for (int k = 0; k < 16; k++) acc[k] = 0.f;
    for (int h = 0; h < 64; h++) {
        float a = wg1[d * 65 + h];
        #pragma unroll
        for (int k = 0; k < 16; k++) acc[k] += a * wg2[h * 64 + i0 + k];
    }
    #pragma unroll
    for (int k = 0; k < 16; k++) g_WG12[m * 4096 + d * 64 + i0 + k] = acc[k];
}

// -------------------- K0: temp_F = (x @ W_F1[i]) * 0.125 ; f_a
__global__ void k0(const float* __restrict__ x, const float* __restrict__ W_F1,
                   const float* __restrict__ W_A, const float* __restrict__ B_A) {
    extern __shared__ float sm[];
    float* xt = sm;             // [64 f][132]
    float* wf = sm + 64 * 132;  // [64 f][64 h]
    float* wa = wf + 4096;      // [64]
    int t  = threadIdx.x;
    int b0 = blockIdx.x * 128;
    int i  = blockIdx.y;

    for (int idx = t; idx < 4096; idx += 256) wf[idx] = W_F1[i * 4096 + idx];
    if (t < 64) wa[t] = W_A[i * 64 + t];
    for (int idx = t; idx < 2048; idx += 256) {
        int b = idx >> 4, f0 = (idx & 15) * 4;
        float4 v = *(const float4*)&x[((b0 + b) * 64 + i) * 64 + f0];
        xt[(f0 + 0) * 132 + b] = v.x;
        xt[(f0 + 1) * 132 + b] = v.y;
        xt[(f0 + 2) * 132 + b] = v.z;
        xt[(f0 + 3) * 132 + b] = v.w;
    }
    __syncthreads();

    int bq = t >> 3, dq = t & 7;
    int bb = bq * 4, d0 = dq * 4, d1 = 32 + dq * 4;
    ull pacc[4][4];
    #pragma unroll
    for (int j = 0; j < 4; j++)
        #pragma unroll
        for (int k = 0; k < 4; k++) pacc[j][k] = 0ull;

    #pragma unroll 4
    for (int f = 0; f < 64; f++) {
        float4 xv = *(float4*)&xt[f * 132 + bb];
        ulonglong2 wA = *(ulonglong2*)&wf[f * 64 + d0];
        ulonglong2 wB = *(ulonglong2*)&wf[f * 64 + d1];
        ull xb[4] = {bcast2(xv.x), bcast2(xv.y), bcast2(xv.z), bcast2(xv.w)};
        #pragma unroll
        for (int j = 0; j < 4; j++) {
            fma2(pacc[j][0], xb[j], wA.x);
            fma2(pacc[j][1], xb[j], wA.y);
            fma2(pacc[j][2], xb[j], wB.x);
            fma2(pacc[j][3], xb[j], wB.y);
        }
    }
    #pragma unroll
    for (int j = 0; j < 4; j++) {
        float2 a0 = unpk(pacc[j][0]), a1 = unpk(pacc[j][1]);
        float2 a2 = unpk(pacc[j][2]), a3 = unpk(pacc[j][3]);
        int base = ((b0 + bb + j) * 64 + i) * 64;
        *(float4*)&g_tempF[base + d0] = make_float4(a0.x * 0.125f, a0.y * 0.125f,
                                                    a1.x * 0.125f, a1.y * 0.125f);
        *(float4*)&g_tempF[base + d1] = make_float4(a2.x * 0.125f, a2.y * 0.125f,
                                                    a3.x * 0.125f, a3.y * 0.125f);
    }

    if (t < 128) {
        int b = t;
        float a = 0.f;
        #pragma unroll 8
        for (int f = 0; f < 64; f++) a = fmaf(xt[f * 132 + b], wa[f], a);
        a = a * 0.125f + B_A[i];
        g_fa[(b0 + b) * 64 + i] = 1.f / (1.f + __expf(-a));
    }
}

// -------------------- ky1: iteration-1 y (s = fa*c0 inline); half-grid (off param)
__global__ void ky1(int boff) {
    int t = threadIdx.x;
    int w = t >> 5, l = t & 31;
    int b = (blockIdx.x + boff) * 8 + w;
    int r = l >> 4, c = l & 15;
    float sA = g_fa[b * 64 + l] * g_c0[l];
    float sB = g_fa[b * 64 + 32 + l] * g_c0[32 + l];
    const float4* tf = (const float4*)(g_tempF + b * 4096);
    float4 acc = make_float4(0.f, 0.f, 0.f, 0.f);
    #pragma unroll
    for (int k = 0; k < 32; k++) {
        int idx = 2 * k + r;
        float sv = (k < 16) ? __shfl_sync(0xffffffffu, sA, idx)
                            : __shfl_sync(0xffffffffu, sB, idx - 32);
        float4 p = tf[idx * 16 + c];
        acc.x = fmaf(sv, p.x, acc.x);
        acc.y = fmaf(sv, p.y, acc.y);
        acc.z = fmaf(sv, p.z, acc.z);
        acc.w = fmaf(sv, p.w, acc.w);
    }
    acc.x += __shfl_xor_sync(0xffffffffu, acc.x, 16);
    acc.y += __shfl_xor_sync(0xffffffffu, acc.y, 16);
    acc.z += __shfl_xor_sync(0xffffffffu, acc.z, 16);
    acc.w += __shfl_xor_sync(0xffffffffu, acc.w, 16);
    if (r == 0) ((float4*)g_y)[b * 16 + c] = acc;
}

// -------------------- kxm: x_out = y@W_F2+B_F2 ; [LN ; xhat = xn@W_G12+B_G2]
// grid (32, 16), 256 threads; single shared w buffer (W_F2 then W_G12)
template <bool LAST>
__global__ void __launch_bounds__(256, 4) kxm(const float* __restrict__ W_F2,
                    const float* __restrict__ B_F2,
                    const float* __restrict__ B_G2, const float* __restrict__ gamma,
                    const float* __restrict__ beta, float* __restrict__ out) {
    extern __shared__ float sm[];
    float* yt = sm;             // [64 h][132]  (xn_t reuses this)
    float* w  = sm + 64 * 132;  // [64][64]  W_F2[m], later W_G12[m]
    int t  = threadIdx.x;
    int b0 = blockIdx.x * 128;
    int m  = blockIdx.y;

    for (int idx = t; idx < 8192; idx += 256) {
        int b = idx >> 6, h = idx & 63;
        yt[h * 132 + b] = g_y[(b0 + b) * 64 + h];
    }
    for (int idx = t; idx < 4096; idx += 256) w[idx] = W_F2[m * 4096 + idx];
    __syncthreads();

    int bq = t >> 3, dq = t & 7;
    int bb = bq * 4, d0 = dq * 4, d1 = 32 + dq * 4;

    ull pacc[4][4];
    #pragma unroll
    for (int j = 0; j < 4; j++)
        #pragma unroll
        for (int k = 0; k < 4; k++) pacc[j][k] = 0ull;

    #pragma unroll 4
    for (int h = 0; h < 64; h++) {
        float4 yv = *(float4*)&yt[h * 132 + bb];
        ulonglong2 wA = *(ulonglong2*)&w[h * 64 + d0];
        ulonglong2 wB = *(ulonglong2*)&w[h * 64 + d1];
        ull yb[4] = {bcast2(yv.x), bcast2(yv.y), bcast2(yv.z), bcast2(yv.w)};
        #pragma unroll
        for (int j = 0; j < 4; j++) {
            fma2(pacc[j][0], yb[j], wA.x);
            fma2(pacc[j][1], yb[j], wA.y);
            fma2(pacc[j][2], yb[j], wB.x);
            fma2(pacc[j][3], yb[j], wB.y);
        }
    }

    float acc[4][8];
    float4 bfA = *(const float4*)&B_F2[m * 64 + d0];
    float4 bfB = *(const float4*)&B_F2[m * 64 + d1];
    #pragma unroll
    for (int j = 0; j < 4; j++) {
        float2 a0 = unpk(pacc[j][0]), a1 = unpk(pacc[j][1]);
        float2 a2 = unpk(pacc[j][2]), a3 = unpk(pacc[j][3]);
        acc[j][0] = a0.x + bfA.x; acc[j][1] = a0.y + bfA.y;
        acc[j][2] = a1.x + bfA.z; acc[j][3] = a1.y + bfA.w;
        acc[j][4] = a2.x + bfB.x; acc[j][5] = a2.y + bfB.y;
        acc[j][6] = a3.x + bfB.z; acc[j][7] = a3.y + bfB.w;
    }

    if (LAST) {
        #pragma unroll
        for (int j = 0; j < 4; j++) {
            int base = ((b0 + bb + j) * 16 + m) * 64;
            *(float4*)&out[base + d0] = make_float4(acc[j][0], acc[j][1], acc[j][2], acc[j][3]);
            *(float4*)&out[base + d1] = make_float4(acc[j][4], acc[j][5], acc[j][6], acc[j][7]);
        }
        return;
    }

    float4 gA = *(const float4*)&gamma[d0];
    float4 gB = *(const float4*)&gamma[d1];
    float4 eA = *(const float4*)&beta[d0];
    float4 eB = *(const float4*)&beta[d1];
    float gam[8] = {gA.x, gA.y, gA.z, gA.w, gB.x, gB.y, gB.z, gB.w};
    float bet[8] = {eA.x, eA.y, eA.z, eA.w, eB.x, eB.y, eB.z, eB.w};

    __syncthreads();   // all yt and w reads done (yt -> xn_t, w -> W_G12)

    // stage W_G12 into the same w buffer (loads issued early, overlap LN)
    for (int idx = t; idx < 4096; idx += 256) w[idx] = g_WG12[m * 4096 + idx];

    float xn[4][8];
    #pragma unroll
    for (int j = 0; j < 4; j++) {
        float s1 = 0.f, s2 = 0.f;
        #pragma unroll
        for (int k = 0; k < 8; k++) { s1 += acc[j][k]; s2 = fmaf(acc[j][k], acc[j][k], s2); }
        #pragma unroll
        for (int off = 1; off < 8; off <<= 1) {
            s1 += __shfl_xor_sync(0xffffffffu, s1, off);
            s2 += __shfl_xor_sync(0xffffffffu, s2, off);
        }
        float mu   = s1 * (1.f / 64.f);
        float var  = s2 * (1.f / 64.f) - mu * mu;
        float rstd = rsqrtf(var + 1e-5f);
        #pragma unroll
        for (int k = 0; k < 8; k++)
            xn[j][k] = fmaf((acc[j][k] - mu) * rstd, gam[k], bet[k]);
    }
    // store xn transposed [d][b]
    #pragma unroll
    for (int j = 0; j < 4; j++) {
        #pragma unroll
        for (int k = 0; k < 4; k++) {
            yt[(d0 + k) * 132 + bb + j] = xn[j][k];
            yt[(d1 + k) * 132 + bb + j] = xn[j][k + 4];
        }
    }
    __syncthreads();

    ull pacc2[4][4];
    #pragma unroll
    for (int j = 0; j < 4; j++)
        #pragma unroll
        for (int k = 0; k < 4; k++) pacc2[j][k] = 0ull;

    #pragma unroll 4
    for (int d = 0; d < 64; d++) {
        float4 xv = *(float4*)&yt[d * 132 + bb];
        ulonglong2 wA = *(ulonglong2*)&w[d * 64 + d0];
        ulonglong2 wB = *(ulonglong2*)&w[d * 64 + d1];
        ull xb[4] = {bcast2(xv.x), bcast2(xv.y), bcast2(xv.z), bcast2(xv.w)};
        #pragma unroll
        for (int j = 0; j < 4; j++) {
            fma2(pacc2[j][0], xb[j], wA.x);
            fma2(pacc2[j][1], xb[j], wA.y);
            fma2(pacc2[j][2], xb[j], wB.x);
            fma2(pacc2[j][3], xb[j], wB.y);
        }
    }
    float4 bgA = *(const float4*)&B_G2[m * 64 + d0];
    float4 bgB = *(const float4*)&B_G2[m * 64 + d1];
    #pragma unroll
    for (int j = 0; j < 4; j++) {
        float2 a0 = unpk(pacc2[j][0]), a1 = unpk(pacc2[j][1]);
        float2 a2 = unpk(pacc2[j][2]), a3 = unpk(pacc2[j][3]);
        int base = ((b0 + bb + j) * 16 + m) * 64;
        *(float4*)&g_xhat[base + d0] = make_float4(a0.x + bgA.x, a0.y + bgA.y,
                                                   a1.x + bgA.z, a1.y + bgA.w);
        *(float4*)&g_xhat[base + d1] = make_float4(a2.x + bgB.x, a2.y + bgB.y,
                                                   a3.x + bgB.z, a3.y + bgB.w);
    }
}

// -------------------- kBy: consistency + softmax + s (4 i per round), then y epilogue
// grid 256 (16 b/CTA), 256 threads (16 b x 16 m)
__global__ void __launch_bounds__(256) kBy(const float* __restrict__ x,
                                           const float* __restrict__ W_S,
                                           const float* __restrict__ B_S) {
    __shared__ float xsm[4][16 * 68];
    __shared__ float ws [4][16 * 68];
    __shared__ float bsum_sm[64 * 16];
    __shared__ float bs_sm  [64 * 16];
    __shared__ float bI_sm  [64];
    __shared__ float s_sm   [16 * 64];
    int t  = threadIdx.x;
    int bl = t >> 4, m = t & 15;
    int b0 = blockIdx.x * 16;
    int b  = b0 + bl;

    ulonglong2 xh2[16];
    const ulonglong2* xp = (const ulonglong2*)(g_xhat + (b * 16 + m) * 64);
    #pragma unroll
    for (int v = 0; v < 16; v++) xh2[v] = xp[v];

    for (int idx = t; idx < 1024; idx += 256) {
        bsum_sm[idx] = g_bsum[idx];
        bs_sm[idx]   = B_S[idx];
    }
    if (t < 64) bI_sm[t] = g_bI[t];

    int bb2 = t >> 4, f0 = (t & 15) * 4;
    float4 px[4], pw[4];
    #pragma unroll
    for (int j = 0; j < 4; j++) {
        px[j] = *(const float4*)&x[((b0 + bb2) * 64 + j) * 64 + f0];
        pw[j] = *(const float4*)&W_S[(j * 16 + bb2) * 64 + f0];
    }
    // f_a for this (b, round): same addr across 16 m lanes -> L1 broadcast
    float4 fa_cur = *(const float4*)&g_fa[b * 64 + 0];

    for (int r = 0; r < 16; r++) {
        int ib = 4 * r;
        __syncthreads();
        #pragma unroll
        for (int j = 0; j < 4; j++) {
            *(float4*)&xsm[j][bb2 * 68 + f0] = px[j];
            *(float4*)&ws [j][bb2 * 68 + f0] = pw[j];
        }
        __syncthreads();
        if (r < 15) {
            #pragma unroll
            for (int j = 0; j < 4; j++) {
                px[j] = *(const float4*)&x[((b0 + bb2) * 64 + ib + 4 + j) * 64 + f0];
                pw[j] = *(const float4*)&W_S[((ib + 4 + j) * 16 + bb2) * 64 + f0];
            }
        }

        ull aA[4], aB[4];
        #pragma unroll
        for (int j = 0; j < 4; j++) { aA[j] = 0ull; aB[j] = 0ull; }
        #pragma unroll
        for (int fq = 0; fq < 16; fq++) {
            #pragma unroll
            for (int j = 0; j < 4; j++) {
                ulonglong2 xv = *(ulonglong2*)&xsm[j][bl * 68 + fq * 4];
                ulonglong2 wv = *(ulonglong2*)&ws [j][m  * 68 + fq * 4];
                fma2(aA[j], mul2(xv.x, wv.x), xh2[fq].x);
                fma2(aB[j], mul2(xv.y, wv.y), xh2[fq].y);
            }
        }
        float acc[4];
        #pragma unroll
        for (int j = 0; j < 4; j++) {
            float2 ra = unpk(aA[j]), rb = unpk(aB[j]);
            acc[j] = bs_sm[(ib + j) * 16 + m] + ((ra.x + ra.y) + (rb.x + rb.y));
        }

        // interleaved 16-lane softmax chains (ILP=4)
        float mx[4];
        #pragma unroll
        for (int j = 0; j < 4; j++) mx[j] = acc[j];
        #pragma unroll
        for (int off = 1; off < 16; off <<= 1) {
            #pragma unroll
            for (int j = 0; j < 4; j++)
                mx[j] = fmaxf(mx[j], __shfl_xor_sync(0xffffffffu, mx[j], off));
        }
        float num[4], den[4];
        #pragma unroll
        for (int j = 0; j < 4; j++) {
            float e = __expf(acc[j] - mx[j]);
            num[j] = e * bsum_sm[(ib + j) * 16 + m];
            den[j] = e;
        }
        #pragma unroll
        for (int off = 1; off < 16; off <<= 1) {
            #pragma unroll
            for (int j = 0; j < 4; j++) {
                num[j] += __shfl_xor_sync(0xffffffffu, num[j], off);
                den[j] += __shfl_xor_sync(0xffffffffu, den[j], off);
            }
        }
        if (m == 0) {
            float fa4[4] = {fa_cur.x, fa_cur.y, fa_cur.z, fa_cur.w};
            #pragma unroll
            for (int j = 0; j < 4; j++)
                s_sm[bl * 64 + ib + j] = fa4[j] * (num[j] / den[j] - bI_sm[ib + j]);
        }
        if (r < 15) fa_cur = *(const float4*)&g_fa[b * 64 + ib + 4];
    }

    // ---- epilogue: y[b, 4m..4m+3] = sum_i s[b,i] * tempF[b,i,4m..4m+3]
    __syncthreads();
    const float4* tfb = (const float4*)(g_tempF + b * 4096) + m;
    float4 yacc = make_float4(0.f, 0.f, 0.f, 0.f);
    #pragma unroll 16
    for (int i = 0; i < 64; i++) {
        float sv = s_sm[bl * 64 + i];
        float4 p = tfb[i * 16];
        yacc.x = fmaf(sv, p.x, yacc.x);
        yacc.y = fmaf(sv, p.y, yacc.y);
        yacc.z = fmaf(sv, p.z, yacc.z);
        yacc.w = fmaf(sv, p.w, yacc.w);
    }
    ((float4*)g_y)[b * 16 + m] = yacc;
}

// ---------------------------------------------------------------- launcher
extern "C" void kernel_launch(void* const* d_in, const int* in_sizes, int n_in,
                              void* d_out, int out_size) {
    const float* x    = (const float*)d_in[0];
    const float* W_A  = (const float*)d_in[1];
    const float* B_A  = (const float*)d_in[2];
    const float* W_F1 = (const float*)d_in[3];
    const float* W_F2 = (const float*)d_in[4];
    const float* B_F2 = (const float*)d_in[5];
    const float* W_G1 = (const float*)d_in[6];
    const float* W_G2 = (const float*)d_in[7];
    const float* B_G2 = (const float*)d_in[8];
    const float* gam  = (const float*)d_in[9];
    const float* bet  = (const float*)d_in[10];
    const float* W_S  = (const float*)d_in[11];
    const float* B_S  = (const float*)d_in[12];
    const float* bu   = (const float*)d_in[13];
    const float* bg   = (const float*)d_in[14];
    float* out = (float*)d_out;

    const int K0_SMEM  = (64 * 132 + 4096 + 64) * 4;     // 50432 B
    const int KXM_SMEM = (64 * 132 + 4096) * 4;          // 50176 B
    cudaFuncSetAttribute(k0, cudaFuncAttributeMaxDynamicSharedMemorySize, K0_SMEM);
    cudaFuncSetAttribute(kxm<false>, cudaFuncAttributeMaxDynamicSharedMemorySize, KXM_SMEM);
    cudaFuncSetAttribute(kxm<true>,  cudaFuncAttributeMaxDynamicSharedMemorySize, KXM_SMEM);

    k_wg12p<<<17, 256>>>(W_G1, W_G2, bu, bg);              // launch 1
    k0<<<dim3(32, 64), 256, K0_SMEM>>>(x, W_F1, W_A, B_A); // launch 2

    // iteration 1
    ky1<<<256, 256>>>(0);                                  // launch 3
    ky1<<<256, 256>>>(256);                                // launch 4
    kxm<false><<<dim3(32, 16), 256, KXM_SMEM>>>(W_F2, B_F2, B_G2, gam, bet, nullptr); // 5
    // iteration 2
    kBy<<<256, 256>>>(x, W_S, B_S);                        // launch 6 (profiled)
    kxm<false><<<dim3(32, 16), 256, KXM_SMEM>>>(W_F2, B_F2, B_G2, gam, bet, nullptr);
    // iteration 3
    kBy<<<256, 256>>>(x, W_S, B_S);
    kxm<true><<<dim3(32, 16), 256, KXM_SMEM>>>(W_F2, B_F2, B_G2, gam, bet, out);
}

// round 12
// speedup vs baseline: 1.0453x; 1.0453x over previous
#include <cuda_runtime.h>
#include <math.h>

#define B_TOT 4096
#define IC 64
#define OC 16
#define DD 64

typedef unsigned long long ull;

static __device__ float g_tempF[B_TOT * IC * DD];   // [b][i][h]
static __device__ float g_xhat [B_TOT * OC * DD];   // [b][m][f]
static __device__ float g_y    [B_TOT * DD];        // [b][h]
static __device__ float g_fa   [B_TOT * IC];
static __device__ float g_WG12 [OC * DD * DD];      // [m][d][f]
static __device__ float g_bsum [IC * OC];
static __device__ float g_bI   [IC];
static __device__ float g_c0   [IC];

// ---- packed f32x2 helpers (Blackwell) ----
__device__ __forceinline__ void fma2(ull& d, ull a, ull b) {
    asm("fma.rn.f32x2 %0, %1, %2, %0;" : "+l"(d) : "l"(a), "l"(b));
}
__device__ __forceinline__ ull mul2(ull a, ull b) {
    ull r; asm("mul.rn.f32x2 %0, %1, %2;" : "=l"(r) : "l"(a), "l"(b)); return r;
}
__device__ __forceinline__ ull bcast2(float x) {
    ull r; asm("mov.b64 %0, {%1, %1};" : "=l"(r) : "r"(__float_as_uint(x))); return r;
}
__device__ __forceinline__ float2 unpk(ull v) {
    float2 f; asm("mov.b64 {%0, %1}, %2;" : "=f"(f.x), "=f"(f.y) : "l"(v)); return f;
}

// -------------------- k_wg12p: blocks 0-15 = W_G12[m]; block 16 = beta prep
__global__ void k_wg12p(const float* __restrict__ W_G1, const float* __restrict__ W_G2,
                        const float* __restrict__ bu, const float* __restrict__ bg) {
    if (blockIdx.x == 16) {
        int i = threadIdx.x;
        if (i < 64) {
            float bi = 0.f, cs = 0.f;
            #pragma unroll
            for (int m = 0; m < OC; m++) {
                float u = bu[i * OC + m], g = bg[i * OC + m];
                float s = u + g;
                g_bsum[i * OC + m] = s;
                bi += g; cs += s;
            }
            g_bI[i] = bi;
            g_c0[i] = cs * (1.f / OC) - bi;
        }
        return;
    }
    __shared__ float wg1[64 * 65];
    __shared__ float wg2[64 * 64];
    int m = blockIdx.x, t = threadIdx.x;
    for (int idx = t; idx < 4096; idx += 256) {
        int d = idx >> 6, h = idx & 63;
        wg1[d * 65 + h] = W_G1[idx];
        wg2[idx]        = W_G2[m * 4096 + idx];
    }
    __syncthreads();
    int d = t >> 2, i0 = (t & 3) * 16;
    float acc[16];
    #pragma unroll
    for (int k = 0; k < 16; k++) acc[k] = 0.f;
    for (int h = 0; h < 64; h++) {
        float a = wg1[d * 65 + h];
        #pragma unroll
        for (int k = 0; k < 16; k++) acc[k] += a * wg2[h * 64 + i0 + k];
    }
    #pragma unroll
    for (int k = 0; k < 16; k++) g_WG12[m * 4096 + d * 64 + i0 + k] = acc[k];
}

// -------------------- K0: temp_F = (x @ W_F1[i]) * 0.125 ; f_a
__global__ void k0(const float* __restrict__ x, const float* __restrict__ W_F1,
                   const float* __restrict__ W_A, const float* __restrict__ B_A) {
    extern __shared__ float sm[];
    float* xt = sm;             // [64 f][132]
    float* wf = sm + 64 * 132;  // [64 f][64 h]
    float* wa = wf + 4096;      // [64]
    int t  = threadIdx.x;
    int b0 = blockIdx.x * 128;
    int i  = blockIdx.y;

    for (int idx = t; idx < 4096; idx += 256) wf[idx] = W_F1[i * 4096 + idx];
    if (t < 64) wa[t] = W_A[i * 64 + t];
    for (int idx = t; idx < 2048; idx += 256) {
        int b = idx >> 4, f0 = (idx & 15) * 4;
        float4 v = *(const float4*)&x[((b0 + b) * 64 + i) * 64 + f0];
        xt[(f0 + 0) * 132 + b] = v.x;
        xt[(f0 + 1) * 132 + b] = v.y;
        xt[(f0 + 2) * 132 + b] = v.z;
        xt[(f0 + 3) * 132 + b] = v.w;
    }
    __syncthreads();

    int bq = t >> 3, dq = t & 7;
    int bb = bq * 4, d0 = dq * 4, d1 = 32 + dq * 4;
    ull pacc[4][4];
    #pragma unroll
    for (int j = 0; j < 4; j++)
        #pragma unroll
        for (int k = 0; k < 4; k++) pacc[j][k] = 0ull;

    #pragma unroll 4
    for (int f = 0; f < 64; f++) {
        float4 xv = *(float4*)&xt[f * 132 + bb];
        ulonglong2 wA = *(ulonglong2*)&wf[f * 64 + d0];
        ulonglong2 wB = *(ulonglong2*)&wf[f * 64 + d1];
        ull xb[4] = {bcast2(xv.x), bcast2(xv.y), bcast2(xv.z), bcast2(xv.w)};
        #pragma unroll
        for (int j = 0; j < 4; j++) {
            fma2(pacc[j][0], xb[j], wA.x);
            fma2(pacc[j][1], xb[j], wA.y);
            fma2(pacc[j][2], xb[j], wB.x);
            fma2(pacc[j][3], xb[j], wB.y);
        }
    }
    #pragma unroll
    for (int j = 0; j < 4; j++) {
        float2 a0 = unpk(pacc[j][0]), a1 = unpk(pacc[j][1]);
        float2 a2 = unpk(pacc[j][2]), a3 = unpk(pacc[j][3]);
        int base = ((b0 + bb + j) * 64 + i) * 64;
        *(float4*)&g_tempF[base + d0] = make_float4(a0.x * 0.125f, a0.y * 0.125f,
                                                    a1.x * 0.125f, a1.y * 0.125f);
        *(float4*)&g_tempF[base + d1] = make_float4(a2.x * 0.125f, a2.y * 0.125f,
                                                    a3.x * 0.125f, a3.y * 0.125f);
    }

    if (t < 128) {
        int b = t;
        float a = 0.f;
        #pragma unroll 8
        for (int f = 0; f < 64; f++) a = fmaf(xt[f * 132 + b], wa[f], a);
        a = a * 0.125f + B_A[i];
        g_fa[(b0 + b) * 64 + i] = 1.f / (1.f + __expf(-a));
    }
}

// -------------------- ky1: iteration-1 y (s = fa*c0 inline)
__global__ void ky1() {
    int t = threadIdx.x;
    int w = t >> 5, l = t & 31;
    int b = blockIdx.x * 8 + w;
    int r = l >> 4, c = l & 15;
    float sA = g_fa[b * 64 + l] * g_c0[l];
    float sB = g_fa[b * 64 + 32 + l] * g_c0[32 + l];
    const float4* tf = (const float4*)(g_tempF + b * 4096);
    float4 acc = make_float4(0.f, 0.f, 0.f, 0.f);
    #pragma unroll
    for (int k = 0; k < 32; k++) {
        int idx = 2 * k + r;
        float sv = (k < 16) ? __shfl_sync(0xffffffffu, sA, idx)
                            : __shfl_sync(0xffffffffu, sB, idx - 32);
        float4 p = tf[idx * 16 + c];
        acc.x = fmaf(sv, p.x, acc.x);
        acc.y = fmaf(sv, p.y, acc.y);
        acc.z = fmaf(sv, p.z, acc.z);
        acc.w = fmaf(sv, p.w, acc.w);
    }
    acc.x += __shfl_xor_sync(0xffffffffu, acc.x, 16);
    acc.y += __shfl_xor_sync(0xffffffffu, acc.y, 16);
    acc.z += __shfl_xor_sync(0xffffffffu, acc.z, 16);
    acc.w += __shfl_xor_sync(0xffffffffu, acc.w, 16);
    if (r == 0) ((float4*)g_y)[b * 16 + c] = acc;
}

// -------------------- kxm: x_out = y@W_F2+B_F2 ; [LN ; xhat = xn@W_G12+B_G2]
// grid (32, 16), 256 threads; single shared w buffer (W_F2 then W_G12)
template <bool LAST>
__global__ void __launch_bounds__(256, 4) kxm(const float* __restrict__ W_F2,
                    const float* __restrict__ B_F2,
                    const float* __restrict__ B_G2, const float* __restrict__ gamma,
                    const float* __restrict__ beta, float* __restrict__ out) {
    extern __shared__ float sm[];
    float* yt = sm;             // [64 h][132]  (xn_t reuses this)
    float* w  = sm + 64 * 132;  // [64][64]  W_F2[m], later W_G12[m]
    int t  = threadIdx.x;
    int b0 = blockIdx.x * 128;
    int m  = blockIdx.y;

    for (int idx = t; idx < 8192; idx += 256) {
        int b = idx >> 6, h = idx & 63;
        yt[h * 132 + b] = g_y[(b0 + b) * 64 + h];
    }
    for (int idx = t; idx < 4096; idx += 256) w[idx] = W_F2[m * 4096 + idx];
    __syncthreads();

    int bq = t >> 3, dq = t & 7;
    int bb = bq * 4, d0 = dq * 4, d1 = 32 + dq * 4;

    ull pacc[4][4];
    #pragma unroll
    for (int j = 0; j < 4; j++)
        #pragma unroll
        for (int k = 0; k < 4; k++) pacc[j][k] = 0ull;

    #pragma unroll 4
    for (int h = 0; h < 64; h++) {
        float4 yv = *(float4*)&yt[h * 132 + bb];
        ulonglong2 wA = *(ulonglong2*)&w[h * 64 + d0];
        ulonglong2 wB = *(ulonglong2*)&w[h * 64 + d1];
        ull yb[4] = {bcast2(yv.x), bcast2(yv.y), bcast2(yv.z), bcast2(yv.w)};
        #pragma unroll
        for (int j = 0; j < 4; j++) {
            fma2(pacc[j][0], yb[j], wA.x);
            fma2(pacc[j][1], yb[j], wA.y);
            fma2(pacc[j][2], yb[j], wB.x);
            fma2(pacc[j][3], yb[j], wB.y);
        }
    }

    float acc[4][8];
    float4 bfA = *(const float4*)&B_F2[m * 64 + d0];
    float4 bfB = *(const float4*)&B_F2[m * 64 + d1];
    #pragma unroll
    for (int j = 0; j < 4; j++) {
        float2 a0 = unpk(pacc[j][0]), a1 = unpk(pacc[j][1]);
        float2 a2 = unpk(pacc[j][2]), a3 = unpk(pacc[j][3]);
        acc[j][0] = a0.x + bfA.x; acc[j][1] = a0.y + bfA.y;
        acc[j][2] = a1.x + bfA.z; acc[j][3] = a1.y + bfA.w;
        acc[j][4] = a2.x + bfB.x; acc[j][5] = a2.y + bfB.y;
        acc[j][6] = a3.x + bfB.z; acc[j][7] = a3.y + bfB.w;
    }

    if (LAST) {
        #pragma unroll
        for (int j = 0; j < 4; j++) {
            int base = ((b0 + bb + j) * 16 + m) * 64;
            *(float4*)&out[base + d0] = make_float4(acc[j][0], acc[j][1], acc[j][2], acc[j][3]);
            *(float4*)&out[base + d1] = make_float4(acc[j][4], acc[j][5], acc[j][6], acc[j][7]);
        }
        return;
    }

    float4 gA = *(const float4*)&gamma[d0];
    float4 gB = *(const float4*)&gamma[d1];
    float4 eA = *(const float4*)&beta[d0];
    float4 eB = *(const float4*)&beta[d1];
    float gam[8] = {gA.x, gA.y, gA.z, gA.w, gB.x, gB.y, gB.z, gB.w};
    float bet[8] = {eA.x, eA.y, eA.z, eA.w, eB.x, eB.y, eB.z, eB.w};

    __syncthreads();   // all yt and w reads done (yt -> xn_t, w -> W_G12)

    // stage W_G12 into the same w buffer (loads issued early, overlap LN)
    for (int idx = t; idx < 4096; idx += 256) w[idx] = g_WG12[m * 4096 + idx];

    float xn[4][8];
    #pragma unroll
    for (int j = 0; j < 4; j++) {
        float s1 = 0.f, s2 = 0.f;
        #pragma unroll
        for (int k = 0; k < 8; k++) { s1 += acc[j][k]; s2 = fmaf(acc[j][k], acc[j][k], s2); }
        #pragma unroll
        for (int off = 1; off < 8; off <<= 1) {
            s1 += __shfl_xor_sync(0xffffffffu, s1, off);
            s2 += __shfl_xor_sync(0xffffffffu, s2, off);
        }
        float mu   = s1 * (1.f / 64.f);
        float var  = s2 * (1.f / 64.f) - mu * mu;
        float rstd = rsqrtf(var + 1e-5f);
        #pragma unroll
        for (int k = 0; k < 8; k++)
            xn[j][k] = fmaf((acc[j][k] - mu) * rstd, gam[k], bet[k]);
    }
    // store xn transposed [d][b]
    #pragma unroll
    for (int j = 0; j < 4; j++) {
        #pragma unroll
        for (int k = 0; k < 4; k++) {
            yt[(d0 + k) * 132 + bb + j] = xn[j][k];
            yt[(d1 + k) * 132 + bb + j] = xn[j][k + 4];
        }
    }
    __syncthreads();

    ull pacc2[4][4];
    #pragma unroll
    for (int j = 0; j < 4; j++)
        #pragma unroll
        for (int k = 0; k < 4; k++) pacc2[j][k] = 0ull;

    #pragma unroll 4
    for (int d = 0; d < 64; d++) {
        float4 xv = *(float4*)&yt[d * 132 + bb];
        ulonglong2 wA = *(ulonglong2*)&w[d * 64 + d0];
        ulonglong2 wB = *(ulonglong2*)&w[d * 64 + d1];
        ull xb[4] = {bcast2(xv.x), bcast2(xv.y), bcast2(xv.z), bcast2(xv.w)};
        #pragma unroll
        for (int j = 0; j < 4; j++) {
            fma2(pacc2[j][0], xb[j], wA.x);
            fma2(pacc2[j][1], xb[j], wA.y);
            fma2(pacc2[j][2], xb[j], wB.x);
            fma2(pacc2[j][3], xb[j], wB.y);
        }
    }
    float4 bgA = *(const float4*)&B_G2[m * 64 + d0];
    float4 bgB = *(const float4*)&B_G2[m * 64 + d1];
    #pragma unroll
    for (int j = 0; j < 4; j++) {
        float2 a0 = unpk(pacc2[j][0]), a1 = unpk(pacc2[j][1]);
        float2 a2 = unpk(pacc2[j][2]), a3 = unpk(pacc2[j][3]);
        int base = ((b0 + bb + j) * 16 + m) * 64;
        *(float4*)&g_xhat[base + d0] = make_float4(a0.x + bgA.x, a0.y + bgA.y,
                                                   a1.x + bgA.z, a1.y + bgA.w);
        *(float4*)&g_xhat[base + d1] = make_float4(a2.x + bgB.x, a2.y + bgB.y,
                                                   a3.x + bgB.z, a3.y + bgB.w);
    }
}

// -------------------- kBy: consistency + softmax + s (2 i/round, 4-buffer ring,
// ONE barrier per round), then y epilogue. grid 256 (16 b/CTA), 256 threads.
__global__ void __launch_bounds__(256) kBy(const float* __restrict__ x,
                                           const float* __restrict__ W_S,
                                           const float* __restrict__ B_S) {
    __shared__ float xsm[4][16 * 68];
    __shared__ float ws [4][16 * 68];
    __shared__ float bsum_sm[64 * 16];
    __shared__ float bs_sm  [64 * 16];
    __shared__ float bI_sm  [64];
    __shared__ float fasm   [16 * 64];
    __shared__ float s_sm   [16 * 64];
    int t  = threadIdx.x;
    int bl = t >> 4, m = t & 15;
    int b0 = blockIdx.x * 16;
    int b  = b0 + bl;

    ulonglong2 xh2[16];
    const ulonglong2* xp = (const ulonglong2*)(g_xhat + (b * 16 + m) * 64);
    #pragma unroll
    for (int v = 0; v < 16; v++) xh2[v] = xp[v];

    for (int idx = t; idx < 1024; idx += 256) {
        bsum_sm[idx] = g_bsum[idx];
        bs_sm[idx]   = B_S[idx];
        fasm[idx]    = g_fa[(b0 + (idx >> 6)) * 64 + (idx & 63)];
    }
    if (t < 64) bI_sm[t] = g_bI[t];

    int bb2 = t >> 4, f0 = (t & 15) * 4;
    // stage round 0 (i = 0, 1) into ring pair 0
    *(float4*)&xsm[0][bb2 * 68 + f0] = *(const float4*)&x[((b0 + bb2) * 64 + 0) * 64 + f0];
    *(float4*)&ws [0][bb2 * 68 + f0] = *(const float4*)&W_S[(0 * 16 + bb2) * 64 + f0];
    *(float4*)&xsm[1][bb2 * 68 + f0] = *(const float4*)&x[((b0 + bb2) * 64 + 1) * 64 + f0];
    *(float4*)&ws [1][bb2 * 68 + f0] = *(const float4*)&W_S[(1 * 16 + bb2) * 64 + f0];
    // prefetch round 1 (i = 2, 3)
    float4 px0 = *(const float4*)&x[((b0 + bb2) * 64 + 2) * 64 + f0];
    float4 pw0 = *(const float4*)&W_S[(2 * 16 + bb2) * 64 + f0];
    float4 px1 = *(const float4*)&x[((b0 + bb2) * 64 + 3) * 64 + f0];
    float4 pw1 = *(const float4*)&W_S[(3 * 16 + bb2) * 64 + f0];
    __syncthreads();

    for (int r = 0; r < 32; r++) {
        int i0 = 2 * r, i1 = 2 * r + 1;
        int cur = (r & 1) << 1;   // 0 or 2
        int nxt = cur ^ 2;
        if (r < 31) {
            *(float4*)&xsm[nxt    ][bb2 * 68 + f0] = px0;
            *(float4*)&ws [nxt    ][bb2 * 68 + f0] = pw0;
            *(float4*)&xsm[nxt + 1][bb2 * 68 + f0] = px1;
            *(float4*)&ws [nxt + 1][bb2 * 68 + f0] = pw1;
        }
        if (r < 30) {
            px0 = *(const float4*)&x[((b0 + bb2) * 64 + i0 + 4) * 64 + f0];
            pw0 = *(const float4*)&W_S[((i0 + 4) * 16 + bb2) * 64 + f0];
            px1 = *(const float4*)&x[((b0 + bb2) * 64 + i1 + 4) * 64 + f0];
            pw1 = *(const float4*)&W_S[((i1 + 4) * 16 + bb2) * 64 + f0];
        }

        ull a0A = 0ull, a0B = 0ull, a1A = 0ull, a1B = 0ull;
        #pragma unroll
        for (int fq = 0; fq < 16; fq++) {
            ulonglong2 xv0 = *(ulonglong2*)&xsm[cur    ][bl * 68 + fq * 4];
            ulonglong2 wv0 = *(ulonglong2*)&ws [cur    ][m  * 68 + fq * 4];
            ulonglong2 xv1 = *(ulonglong2*)&xsm[cur + 1][bl * 68 + fq * 4];
            ulonglong2 wv1 = *(ulonglong2*)&ws [cur + 1][m  * 68 + fq * 4];
            fma2(a0A, mul2(xv0.x, wv0.x), xh2[fq].x);
            fma2(a0B, mul2(xv0.y, wv0.y), xh2[fq].y);
            fma2(a1A, mul2(xv1.x, wv1.x), xh2[fq].x);
            fma2(a1B, mul2(xv1.y, wv1.y), xh2[fq].y);
        }
        float2 r0a = unpk(a0A), r0b = unpk(a0B);
        float2 r1a = unpk(a1A), r1b = unpk(a1B);
        float acc0 = bs_sm[i0 * 16 + m] + ((r0a.x + r0a.y) + (r0b.x + r0b.y));
        float acc1 = bs_sm[i1 * 16 + m] + ((r1a.x + r1a.y) + (r1b.x + r1b.y));

        // interleaved 16-lane softmax chains (ILP=2)
        float mx0 = acc0, mx1 = acc1;
        #pragma unroll
        for (int off = 1; off < 16; off <<= 1) {
            mx0 = fmaxf(mx0, __shfl_xor_sync(0xffffffffu, mx0, off));
            mx1 = fmaxf(mx1, __shfl_xor_sync(0xffffffffu, mx1, off));
        }
        float e0 = __expf(acc0 - mx0);
        float e1 = __expf(acc1 - mx1);
        float num0 = e0 * bsum_sm[i0 * 16 + m], den0 = e0;
        float num1 = e1 * bsum_sm[i1 * 16 + m], den1 = e1;
        #pragma unroll
        for (int off = 1; off < 16; off <<= 1) {
            num0 += __shfl_xor_sync(0xffffffffu, num0, off);
            den0 += __shfl_xor_sync(0xffffffffu, den0, off);
            num1 += __shfl_xor_sync(0xffffffffu, num1, off);
            den1 += __shfl_xor_sync(0xffffffffu, den1, off);
        }
        if (m == 0) {
            s_sm[bl * 64 + i0] = fasm[bl * 64 + i0] * (num0 / den0 - bI_sm[i0]);
            s_sm[bl * 64 + i1] = fasm[bl * 64 + i1] * (num1 / den1 - bI_sm[i1]);
        }
        __syncthreads();   // single barrier per round (ring buffers)
    }

    // ---- epilogue: y[b, 4m..4m+3] = sum_i s[b,i] * tempF[b,i,4m..4m+3]
    const float4* tfb = (const float4*)(g_tempF + b * 4096) + m;
    float4 yacc = make_float4(0.f, 0.f, 0.f, 0.f);
    #pragma unroll 16
    for (int i = 0; i < 64; i++) {
        float sv = s_sm[bl * 64 + i];
        float4 p = tfb[i * 16];
        yacc.x = fmaf(sv, p.x, yacc.x);
        yacc.y = fmaf(sv, p.y, yacc.y);
        yacc.z = fmaf(sv, p.z, yacc.z);
        yacc.w = fmaf(sv, p.w, yacc.w);
    }
    ((float4*)g_y)[b * 16 + m] = yacc;
}

// ---------------------------------------------------------------- launcher
extern "C" void kernel_launch(void* const* d_in, const int* in_sizes, int n_in,
                              void* d_out, int out_size) {
    const float* x    = (const float*)d_in[0];
    const float* W_A  = (const float*)d_in[1];
    const float* B_A  = (const float*)d_in[2];
    const float* W_F1 = (const float*)d_in[3];
    const float* W_F2 = (const float*)d_in[4];
    const float* B_F2 = (const float*)d_in[5];
    const float* W_G1 = (const float*)d_in[6];
    const float* W_G2 = (const float*)d_in[7];
    const float* B_G2 = (const float*)d_in[8];
    const float* gam  = (const float*)d_in[9];
    const float* bet  = (const float*)d_in[10];
    const float* W_S  = (const float*)d_in[11];
    const float* B_S  = (const float*)d_in[12];
    const float* bu   = (const float*)d_in[13];
    const float* bg   = (const float*)d_in[14];
    float* out = (float*)d_out;

    const int K0_SMEM  = (64 * 132 + 4096 + 64) * 4;     // 50432 B
    const int KXM_SMEM = (64 * 132 + 4096) * 4;          // 50176 B
    cudaFuncSetAttribute(k0, cudaFuncAttributeMaxDynamicSharedMemorySize, K0_SMEM);
    cudaFuncSetAttribute(kxm<false>, cudaFuncAttributeMaxDynamicSharedMemorySize, KXM_SMEM);
    cudaFuncSetAttribute(kxm<true>,  cudaFuncAttributeMaxDynamicSharedMemorySize, KXM_SMEM);

    k_wg12p<<<17, 256>>>(W_G1, W_G2, bu, bg);
    k0<<<dim3(32, 64), 256, K0_SMEM>>>(x, W_F1, W_A, B_A);

    // iteration 1
    ky1<<<512, 256>>>();
    kxm<false><<<dim3(32, 16), 256, KXM_SMEM>>>(W_F2, B_F2, B_G2, gam, bet, nullptr);
    // iteration 2
    kBy<<<256, 256>>>(x, W_S, B_S);
    kxm<false><<<dim3(32, 16), 256, KXM_SMEM>>>(W_F2, B_F2, B_G2, gam, bet, nullptr);
    // iteration 3
    kBy<<<256, 256>>>(x, W_S, B_S);
    kxm<true><<<dim3(32, 16), 256, KXM_SMEM>>>(W_F2, B_F2, B_G2, gam, bet, out);
}

// round 13
// speedup vs baseline: 1.0567x; 1.0110x over previous
#include <cuda_runtime.h>
#include <math.h>

#define B_TOT 4096
#define IC 64
#define OC 16
#define DD 64

typedef unsigned long long ull;

static __device__ float g_tempF[B_TOT * IC * DD];   // [b][i][h]
static __device__ float g_xhat [B_TOT * OC * DD];   // [b][m][f]
static __device__ float g_y    [B_TOT * DD];        // [b][h]
static __device__ float g_fa   [B_TOT * IC];
static __device__ float g_WG12 [OC * DD * DD];      // [m][d][f]
static __device__ float g_bsum [IC * OC];
static __device__ float g_bI   [IC];
static __device__ float g_c0   [IC];

// ---- packed f32x2 helpers (Blackwell) ----
__device__ __forceinline__ void fma2(ull& d, ull a, ull b) {
    asm("fma.rn.f32x2 %0, %1, %2, %0;" : "+l"(d) : "l"(a), "l"(b));
}
__device__ __forceinline__ ull mul2(ull a, ull b) {
    ull r; asm("mul.rn.f32x2 %0, %1, %2;" : "=l"(r) : "l"(a), "l"(b)); return r;
}
__device__ __forceinline__ ull bcast2(float x) {
    ull r; asm("mov.b64 %0, {%1, %1};" : "=l"(r) : "r"(__float_as_uint(x))); return r;
}
__device__ __forceinline__ float2 unpk(ull v) {
    float2 f; asm("mov.b64 {%0, %1}, %2;" : "=f"(f.x), "=f"(f.y) : "l"(v)); return f;
}

// -------------------- k_wg12p: blocks 0-15 = W_G12[m]; block 16 = beta prep
__global__ void k_wg12p(const float* __restrict__ W_G1, const float* __restrict__ W_G2,
                        const float* __restrict__ bu, const float* __restrict__ bg) {
    if (blockIdx.x == 16) {
        int i = threadIdx.x;
        if (i < 64) {
            float bi = 0.f, cs = 0.f;
            #pragma unroll
            for (int m = 0; m < OC; m++) {
                float u = bu[i * OC + m], g = bg[i * OC + m];
                float s = u + g;
                g_bsum[i * OC + m] = s;
                bi += g; cs += s;
            }
            g_bI[i] = bi;
            g_c0[i] = cs * (1.f / OC) - bi;
        }
        return;
    }
    __shared__ float wg1[64 * 65];
    __shared__ float wg2[64 * 64];
    int m = blockIdx.x, t = threadIdx.x;
    for (int idx = t; idx < 4096; idx += 256) {
        int d = idx >> 6, h = idx & 63;
        wg1[d * 65 + h] = W_G1[idx];
        wg2[idx]        = W_G2[m * 4096 + idx];
    }
    __syncthreads();
    int d = t >> 2, i0 = (t & 3) * 16;
    float acc[16];
    #pragma unroll
    for (int k = 0; k < 16; k++) acc[k] = 0.f;
    for (int h = 0; h < 64; h++) {
        float a = wg1[d * 65 + h];
        #pragma unroll
        for (int k = 0; k < 16; k++) acc[k] += a * wg2[h * 64 + i0 + k];
    }
    #pragma unroll
    for (int k = 0; k < 16; k++) g_WG12[m * 4096 + d * 64 + i0 + k] = acc[k];
}

// -------------------- K0: temp_F = (x @ W_F1[i]) * 0.125 ; f_a
// grid (16, 64): 256-b tile, 256 threads = 32 bq x 8 dq, thread = 8b x 8d
__global__ void __launch_bounds__(256) k0(const float* __restrict__ x,
                   const float* __restrict__ W_F1,
                   const float* __restrict__ W_A, const float* __restrict__ B_A) {
    extern __shared__ float sm[];
    float* xt = sm;              // [64 f][260]  (b transposed)
    float* wf = sm + 64 * 260;   // [64 f][64 h]
    float* wa = wf + 4096;       // [64]
    int t  = threadIdx.x;
    int b0 = blockIdx.x * 256;
    int i  = blockIdx.y;

    for (int idx = t; idx < 4096; idx += 256) wf[idx] = W_F1[i * 4096 + idx];
    if (t < 64) wa[t] = W_A[i * 64 + t];
    for (int idx = t; idx < 4096; idx += 256) {
        int b = idx >> 4, f0 = (idx & 15) * 4;
        float4 v = *(const float4*)&x[((b0 + b) * 64 + i) * 64 + f0];
        xt[(f0 + 0) * 260 + b] = v.x;
        xt[(f0 + 1) * 260 + b] = v.y;
        xt[(f0 + 2) * 260 + b] = v.z;
        xt[(f0 + 3) * 260 + b] = v.w;
    }
    __syncthreads();

    int bq = t >> 3, dq = t & 7;
    int bb = bq * 8, d0 = dq * 4, d1 = 32 + dq * 4;
    ull pacc[8][4];
    #pragma unroll
    for (int j = 0; j < 8; j++)
        #pragma unroll
        for (int k = 0; k < 4; k++) pacc[j][k] = 0ull;

    #pragma unroll 4
    for (int f = 0; f < 64; f++) {
        float4 xv0 = *(float4*)&xt[f * 260 + bb];
        float4 xv1 = *(float4*)&xt[f * 260 + bb + 4];
        ulonglong2 wA = *(ulonglong2*)&wf[f * 64 + d0];
        ulonglong2 wB = *(ulonglong2*)&wf[f * 64 + d1];
        ull xb[8] = {bcast2(xv0.x), bcast2(xv0.y), bcast2(xv0.z), bcast2(xv0.w),
                     bcast2(xv1.x), bcast2(xv1.y), bcast2(xv1.z), bcast2(xv1.w)};
        #pragma unroll
        for (int j = 0; j < 8; j++) {
            fma2(pacc[j][0], xb[j], wA.x);
            fma2(pacc[j][1], xb[j], wA.y);
            fma2(pacc[j][2], xb[j], wB.x);
            fma2(pacc[j][3], xb[j], wB.y);
        }
    }
    #pragma unroll
    for (int j = 0; j < 8; j++) {
        float2 a0 = unpk(pacc[j][0]), a1 = unpk(pacc[j][1]);
        float2 a2 = unpk(pacc[j][2]), a3 = unpk(pacc[j][3]);
        int base = ((b0 + bb + j) * 64 + i) * 64;
        *(float4*)&g_tempF[base + d0] = make_float4(a0.x * 0.125f, a0.y * 0.125f,
                                                    a1.x * 0.125f, a1.y * 0.125f);
        *(float4*)&g_tempF[base + d1] = make_float4(a2.x * 0.125f, a2.y * 0.125f,
                                                    a3.x * 0.125f, a3.y * 0.125f);
    }

    {
        int b = t;   // 256 threads cover all 256 b
        float a = 0.f;
        #pragma unroll 8
        for (int f = 0; f < 64; f++) a = fmaf(xt[f * 260 + b], wa[f], a);
        a = a * 0.125f + B_A[i];
        g_fa[(b0 + b) * 64 + i] = 1.f / (1.f + __expf(-a));
    }
}

// -------------------- ky1: iteration-1 y (s = fa*c0 inline)
__global__ void ky1() {
    int t = threadIdx.x;
    int w = t >> 5, l = t & 31;
    int b = blockIdx.x * 8 + w;
    int r = l >> 4, c = l & 15;
    float sA = g_fa[b * 64 + l] * g_c0[l];
    float sB = g_fa[b * 64 + 32 + l] * g_c0[32 + l];
    const float4* tf = (const float4*)(g_tempF + b * 4096);
    float4 acc = make_float4(0.f, 0.f, 0.f, 0.f);
    #pragma unroll
    for (int k = 0; k < 32; k++) {
        int idx = 2 * k + r;
        float sv = (k < 16) ? __shfl_sync(0xffffffffu, sA, idx)
                            : __shfl_sync(0xffffffffu, sB, idx - 32);
        float4 p = tf[idx * 16 + c];
        acc.x = fmaf(sv, p.x, acc.x);
        acc.y = fmaf(sv, p.y, acc.y);
        acc.z = fmaf(sv, p.z, acc.z);
        acc.w = fmaf(sv, p.w, acc.w);
    }
    acc.x += __shfl_xor_sync(0xffffffffu, acc.x, 16);
    acc.y += __shfl_xor_sync(0xffffffffu, acc.y, 16);
    acc.z += __shfl_xor_sync(0xffffffffu, acc.z, 16);
    acc.w += __shfl_xor_sync(0xffffffffu, acc.w, 16);
    if (r == 0) ((float4*)g_y)[b * 16 + c] = acc;
}

// -------------------- kxm: x_out = y@W_F2+B_F2 ; [LN ; xhat = xn@W_G12+B_G2]
// grid (32, 16), 256 threads; single shared w buffer (W_F2 then W_G12)
template <bool LAST>
__global__ void __launch_bounds__(256, 4) kxm(const float* __restrict__ W_F2,
                    const float* __restrict__ B_F2,
                    const float* __restrict__ B_G2, const float* __restrict__ gamma,
                    const float* __restrict__ beta, float* __restrict__ out) {
    extern __shared__ float sm[];
    float* yt = sm;             // [64 h][132]  (xn_t reuses this)
    float* w  = sm + 64 * 132;  // [64][64]  W_F2[m], later W_G12[m]
    int t  = threadIdx.x;
    int b0 = blockIdx.x * 128;
    int m  = blockIdx.y;

    for (int idx = t; idx < 8192; idx += 256) {
        int b = idx >> 6, h = idx & 63;
        yt[h * 132 + b] = g_y[(b0 + b) * 64 + h];
    }
    for (int idx = t; idx < 4096; idx += 256) w[idx] = W_F2[m * 4096 + idx];
    __syncthreads();

    int bq = t >> 3, dq = t & 7;
    int bb = bq * 4, d0 = dq * 4, d1 = 32 + dq * 4;

    ull pacc[4][4];
    #pragma unroll
    for (int j = 0; j < 4; j++)
        #pragma unroll
        for (int k = 0; k < 4; k++) pacc[j][k] = 0ull;

    #pragma unroll 4
    for (int h = 0; h < 64; h++) {
        float4 yv = *(float4*)&yt[h * 132 + bb];
        ulonglong2 wA = *(ulonglong2*)&w[h * 64 + d0];
        ulonglong2 wB = *(ulonglong2*)&w[h * 64 + d1];
        ull yb[4] = {bcast2(yv.x), bcast2(yv.y), bcast2(yv.z), bcast2(yv.w)};
        #pragma unroll
        for (int j = 0; j < 4; j++) {
            fma2(pacc[j][0], yb[j], wA.x);
            fma2(pacc[j][1], yb[j], wA.y);
            fma2(pacc[j][2], yb[j], wB.x);
            fma2(pacc[j][3], yb[j], wB.y);
        }
    }

    float acc[4][8];
    float4 bfA = *(const float4*)&B_F2[m * 64 + d0];
    float4 bfB = *(const float4*)&B_F2[m * 64 + d1];
    #pragma unroll
    for (int j = 0; j < 4; j++) {
        float2 a0 = unpk(pacc[j][0]), a1 = unpk(pacc[j][1]);
        float2 a2 = unpk(pacc[j][2]), a3 = unpk(pacc[j][3]);
        acc[j][0] = a0.x + bfA.x; acc[j][1] = a0.y + bfA.y;
        acc[j][2] = a1.x + bfA.z; acc[j][3] = a1.y + bfA.w;
        acc[j][4] = a2.x + bfB.x; acc[j][5] = a2.y + bfB.y;
        acc[j][6] = a3.x + bfB.z; acc[j][7] = a3.y + bfB.w;
    }

    if (LAST) {
        #pragma unroll
        for (int j = 0; j < 4; j++) {
            int base = ((b0 + bb + j) * 16 + m) * 64;
            *(float4*)&out[base + d0] = make_float4(acc[j][0], acc[j][1], acc[j][2], acc[j][3]);
            *(float4*)&out[base + d1] = make_float4(acc[j][4], acc[j][5], acc[j][6], acc[j][7]);
        }
        return;
    }

    float4 gA = *(const float4*)&gamma[d0];
    float4 gB = *(const float4*)&gamma[d1];
    float4 eA = *(const float4*)&beta[d0];
    float4 eB = *(const float4*)&beta[d1];
    float gam[8] = {gA.x, gA.y, gA.z, gA.w, gB.x, gB.y, gB.z, gB.w};
    float bet[8] = {eA.x, eA.y, eA.z, eA.w, eB.x, eB.y, eB.z, eB.w};

    __syncthreads();   // all yt and w reads done (yt -> xn_t, w -> W_G12)

    // stage W_G12 into the same w buffer (loads issued early, overlap LN)
    for (int idx = t; idx < 4096; idx += 256) w[idx] = g_WG12[m * 4096 + idx];

    float xn[4][8];
    #pragma unroll
    for (int j = 0; j < 4; j++) {
        float s1 = 0.f, s2 = 0.f;
        #pragma unroll
        for (int k = 0; k < 8; k++) { s1 += acc[j][k]; s2 = fmaf(acc[j][k], acc[j][k], s2); }
        #pragma unroll
        for (int off = 1; off < 8; off <<= 1) {
            s1 += __shfl_xor_sync(0xffffffffu, s1, off);
            s2 += __shfl_xor_sync(0xffffffffu, s2, off);
        }
        float mu   = s1 * (1.f / 64.f);
        float var  = s2 * (1.f / 64.f) - mu * mu;
        float rstd = rsqrtf(var + 1e-5f);
        #pragma unroll
        for (int k = 0; k < 8; k++)
            xn[j][k] = fmaf((acc[j][k] - mu) * rstd, gam[k], bet[k]);
    }
    // store xn transposed [d][b]
    #pragma unroll
    for (int j = 0; j < 4; j++) {
        #pragma unroll
        for (int k = 0; k < 4; k++) {
            yt[(d0 + k) * 132 + bb + j] = xn[j][k];
            yt[(d1 + k) * 132 + bb + j] = xn[j][k + 4];
        }
    }
    __syncthreads();

    ull pacc2[4][4];
    #pragma unroll
    for (int j = 0; j < 4; j++)
        #pragma unroll
        for (int k = 0; k < 4; k++) pacc2[j][k] = 0ull;

    #pragma unroll 4
    for (int d = 0; d < 64; d++) {
        float4 xv = *(float4*)&yt[d * 132 + bb];
        ulonglong2 wA = *(ulonglong2*)&w[d * 64 + d0];
        ulonglong2 wB = *(ulonglong2*)&w[d * 64 + d1];
        ull xb[4] = {bcast2(xv.x), bcast2(xv.y), bcast2(xv.z), bcast2(xv.w)};
        #pragma unroll
        for (int j = 0; j < 4; j++) {
            fma2(pacc2[j][0], xb[j], wA.x);
            fma2(pacc2[j][1], xb[j], wA.y);
            fma2(pacc2[j][2], xb[j], wB.x);
            fma2(pacc2[j][3], xb[j], wB.y);
        }
    }
    float4 bgA = *(const float4*)&B_G2[m * 64 + d0];
    float4 bgB = *(const float4*)&B_G2[m * 64 + d1];
    #pragma unroll
    for (int j = 0; j < 4; j++) {
        float2 a0 = unpk(pacc2[j][0]), a1 = unpk(pacc2[j][1]);
        float2 a2 = unpk(pacc2[j][2]), a3 = unpk(pacc2[j][3]);
        int base = ((b0 + bb + j) * 16 + m) * 64;
        *(float4*)&g_xhat[base + d0] = make_float4(a0.x + bgA.x, a0.y + bgA.y,
                                                   a1.x + bgA.z, a1.y + bgA.w);
        *(float4*)&g_xhat[base + d1] = make_float4(a2.x + bgB.x, a2.y + bgB.y,
                                                   a3.x + bgB.z, a3.y + bgB.w);
    }
}

// -------------------- kBy (R10-validated): consistency + softmax + s (2 i per round),
// then y epilogue. grid 256 (16 b/CTA), 256 threads (16 b x 16 m)
__global__ void __launch_bounds__(256) kBy(const float* __restrict__ x,
                                           const float* __restrict__ W_S,
                                           const float* __restrict__ B_S) {
    __shared__ float xsm[2][16 * 68];
    __shared__ float ws [2][16 * 68];
    __shared__ float bsum_sm[64 * 16];
    __shared__ float bs_sm  [64 * 16];
    __shared__ float bI_sm  [64];
    __shared__ float fasm   [16 * 64];
    __shared__ float s_sm   [16 * 64];
    int t  = threadIdx.x;
    int bl = t >> 4, m = t & 15;
    int b0 = blockIdx.x * 16;
    int b  = b0 + bl;

    ulonglong2 xh2[16];
    const ulonglong2* xp = (const ulonglong2*)(g_xhat + (b * 16 + m) * 64);
    #pragma unroll
    for (int v = 0; v < 16; v++) xh2[v] = xp[v];

    for (int idx = t; idx < 1024; idx += 256) {
        bsum_sm[idx] = g_bsum[idx];
        bs_sm[idx]   = B_S[idx];
        fasm[idx]    = g_fa[(b0 + (idx >> 6)) * 64 + (idx & 63)];
    }
    if (t < 64) bI_sm[t] = g_bI[t];

    int bb2 = t >> 4, f0 = (t & 15) * 4;
    float4 px0 = *(const float4*)&x[((b0 + bb2) * 64 + 0) * 64 + f0];
    float4 pw0 = *(const float4*)&W_S[(0 * 16 + bb2) * 64 + f0];
    float4 px1 = *(const float4*)&x[((b0 + bb2) * 64 + 1) * 64 + f0];
    float4 pw1 = *(const float4*)&W_S[(1 * 16 + bb2) * 64 + f0];

    for (int r = 0; r < 32; r++) {
        int i0 = 2 * r, i1 = 2 * r + 1;
        __syncthreads();
        *(float4*)&xsm[0][bb2 * 68 + f0] = px0;
        *(float4*)&ws [0][bb2 * 68 + f0] = pw0;
        *(float4*)&xsm[1][bb2 * 68 + f0] = px1;
        *(float4*)&ws [1][bb2 * 68 + f0] = pw1;
        __syncthreads();
        if (r < 31) {
            px0 = *(const float4*)&x[((b0 + bb2) * 64 + i0 + 2) * 64 + f0];
            pw0 = *(const float4*)&W_S[((i0 + 2) * 16 + bb2) * 64 + f0];
            px1 = *(const float4*)&x[((b0 + bb2) * 64 + i1 + 2) * 64 + f0];
            pw1 = *(const float4*)&W_S[((i1 + 2) * 16 + bb2) * 64 + f0];
        }

        ull a0A = 0ull, a0B = 0ull, a1A = 0ull, a1B = 0ull;
        #pragma unroll
        for (int fq = 0; fq < 16; fq++) {
            ulonglong2 xv0 = *(ulonglong2*)&xsm[0][bl * 68 + fq * 4];
            ulonglong2 wv0 = *(ulonglong2*)&ws [0][m  * 68 + fq * 4];
            ulonglong2 xv1 = *(ulonglong2*)&xsm[1][bl * 68 + fq * 4];
            ulonglong2 wv1 = *(ulonglong2*)&ws [1][m  * 68 + fq * 4];
            fma2(a0A, mul2(xv0.x, wv0.x), xh2[fq].x);
            fma2(a0B, mul2(xv0.y, wv0.y), xh2[fq].y);
            fma2(a1A, mul2(xv1.x, wv1.x), xh2[fq].x);
            fma2(a1B, mul2(xv1.y, wv1.y), xh2[fq].y);
        }
        float2 r0a = unpk(a0A), r0b = unpk(a0B);
        float2 r1a = unpk(a1A), r1b = unpk(a1B);
        float acc0 = bs_sm[i0 * 16 + m] + ((r0a.x + r0a.y) + (r0b.x + r0b.y));
        float acc1 = bs_sm[i1 * 16 + m] + ((r1a.x + r1a.y) + (r1b.x + r1b.y));

        // interleaved 16-lane softmax chains (ILP=2)
        float mx0 = acc0, mx1 = acc1;
        #pragma unroll
        for (int off = 1; off < 16; off <<= 1) {
            mx0 = fmaxf(mx0, __shfl_xor_sync(0xffffffffu, mx0, off));
            mx1 = fmaxf(mx1, __shfl_xor_sync(0xffffffffu, mx1, off));
        }
        float e0 = __expf(acc0 - mx0);
        float e1 = __expf(acc1 - mx1);
        float num0 = e0 * bsum_sm[i0 * 16 + m], den0 = e0;
        float num1 = e1 * bsum_sm[i1 * 16 + m], den1 = e1;
        #pragma unroll
        for (int off = 1; off < 16; off <<= 1) {
            num0 += __shfl_xor_sync(0xffffffffu, num0, off);
            den0 += __shfl_xor_sync(0xffffffffu, den0, off);
            num1 += __shfl_xor_sync(0xffffffffu, num1, off);
            den1 += __shfl_xor_sync(0xffffffffu, den1, off);
        }
        if (m == 0) {
            s_sm[bl * 64 + i0] = fasm[bl * 64 + i0] * (num0 / den0 - bI_sm[i0]);
            s_sm[bl * 64 + i1] = fasm[bl * 64 + i1] * (num1 / den1 - bI_sm[i1]);
        }
    }

    // ---- epilogue: y[b, 4m..4m+3] = sum_i s[b,i] * tempF[b,i,4m..4m+3]
    __syncthreads();
    const float4* tfb = (const float4*)(g_tempF + b * 4096) + m;
    float4 yacc = make_float4(0.f, 0.f, 0.f, 0.f);
    #pragma unroll 16
    for (int i = 0; i < 64; i++) {
        float sv = s_sm[bl * 64 + i];
        float4 p = tfb[i * 16];
        yacc.x = fmaf(sv, p.x, yacc.x);
        yacc.y = fmaf(sv, p.y, yacc.y);
        yacc.z = fmaf(sv, p.z, yacc.z);
        yacc.w = fmaf(sv, p.w, yacc.w);
    }
    ((float4*)g_y)[b * 16 + m] = yacc;
}

// ---------------------------------------------------------------- launcher
extern "C" void kernel_launch(void* const* d_in, const int* in_sizes, int n_in,
                              void* d_out, int out_size) {
    const float* x    = (const float*)d_in[0];
    const float* W_A  = (const float*)d_in[1];
    const float* B_A  = (const float*)d_in[2];
    const float* W_F1 = (const float*)d_in[3];
    const float* W_F2 = (const float*)d_in[4];
    const float* B_F2 = (const float*)d_in[5];
    const float* W_G1 = (const float*)d_in[6];
    const float* W_G2 = (const float*)d_in[7];
    const float* B_G2 = (const float*)d_in[8];
    const float* gam  = (const float*)d_in[9];
    const float* bet  = (const float*)d_in[10];
    const float* W_S  = (const float*)d_in[11];
    const float* B_S  = (const float*)d_in[12];
    const float* bu   = (const float*)d_in[13];
    const float* bg   = (const float*)d_in[14];
    float* out = (float*)d_out;

    const int K0_SMEM  = (64 * 260 + 4096 + 64) * 4;     // 83200 B
    const int KXM_SMEM = (64 * 132 + 4096) * 4;          // 50176 B
    cudaFuncSetAttribute(k0, cudaFuncAttributeMaxDynamicSharedMemorySize, K0_SMEM);
    cudaFuncSetAttribute(kxm<false>, cudaFuncAttributeMaxDynamicSharedMemorySize, KXM_SMEM);
    cudaFuncSetAttribute(kxm<true>,  cudaFuncAttributeMaxDynamicSharedMemorySize, KXM_SMEM);

    k_wg12p<<<17, 256>>>(W_G1, W_G2, bu, bg);
    k0<<<dim3(16, 64), 256, K0_SMEM>>>(x, W_F1, W_A, B_A);

    // iteration 1
    ky1<<<512, 256>>>();
    kxm<false><<<dim3(32, 16), 256, KXM_SMEM>>>(W_F2, B_F2, B_G2, gam, bet, nullptr);
    // iteration 2
    kBy<<<256, 256>>>(x, W_S, B_S);
    kxm<false><<<dim3(32, 16), 256, KXM_SMEM>>>(W_F2, B_F2, B_G2, gam, bet, nullptr);
    // iteration 3
    kBy<<<256, 256>>>(x, W_S, B_S);
    kxm<true><<<dim3(32, 16), 256, KXM_SMEM>>>(W_F2, B_F2, B_G2, gam, bet, out);
}

// round 14
// speedup vs baseline: 1.1368x; 1.0757x over previous
#include <cuda_runtime.h>
#include <math.h>

#define B_TOT 4096
#define IC 64
#define OC 16
#define DD 64

typedef unsigned long long ull;

static __device__ float g_tempF[B_TOT * IC * DD];   // [b][i][h]
static __device__ float g_xhat [B_TOT * OC * DD];   // [b][m][f]
static __device__ float g_y    [B_TOT * DD];        // [b][h]
static __device__ float g_fa   [B_TOT * IC];
static __device__ float g_WG12 [OC * DD * DD];      // [m][d][f]
static __device__ float g_bsum [IC * OC];
static __device__ float g_bI   [IC];
static __device__ float g_c0   [IC];

// ---- packed f32x2 helpers (Blackwell) ----
__device__ __forceinline__ void fma2(ull& d, ull a, ull b) {
    asm("fma.rn.f32x2 %0, %1, %2, %0;" : "+l"(d) : "l"(a), "l"(b));
}
__device__ __forceinline__ ull mul2(ull a, ull b) {
    ull r; asm("mul.rn.f32x2 %0, %1, %2;" : "=l"(r) : "l"(a), "l"(b)); return r;
}
__device__ __forceinline__ ull bcast2(float x) {
    ull r; asm("mov.b64 %0, {%1, %1};" : "=l"(r) : "r"(__float_as_uint(x))); return r;
}
__device__ __forceinline__ float2 unpk(ull v) {
    float2 f; asm("mov.b64 {%0, %1}, %2;" : "=f"(f.x), "=f"(f.y) : "l"(v)); return f;
}

// -------------------- K0 (R10 body) + folded prep plane (blockIdx.y == 64):
//   y<64 : temp_F = (x @ W_F1[i]) * 0.125 ; f_a     [grid (32, 64), 128-b tile]
//   y==64: x<16 -> W_G12[m] = W_G1@W_G2[m]; x==16 -> beta prep; x>16 -> noop
__global__ void k0(const float* __restrict__ x, const float* __restrict__ W_F1,
                   const float* __restrict__ W_A, const float* __restrict__ B_A,
                   const float* __restrict__ W_G1, const float* __restrict__ W_G2,
                   const float* __restrict__ bu, const float* __restrict__ bg) {
    extern __shared__ float sm[];
    int t = threadIdx.x;

    if (blockIdx.y == 64) {
        if (blockIdx.x == 16) {
            int i = t;
            if (i < 64) {
                float bi = 0.f, cs = 0.f;
                #pragma unroll
                for (int m = 0; m < OC; m++) {
                    float u = bu[i * OC + m], g = bg[i * OC + m];
                    float s = u + g;
                    g_bsum[i * OC + m] = s;
                    bi += g; cs += s;
                }
                g_bI[i] = bi;
                g_c0[i] = cs * (1.f / OC) - bi;
            }
            return;
        }
        if (blockIdx.x > 16) return;
        // W_G12[m] = W_G1 @ W_G2[m]
        float* wg1 = sm;            // [64][65]
        float* wg2 = sm + 64 * 65;  // [64][64]
        int m = blockIdx.x;
        for (int idx = t; idx < 4096; idx += 256) {
            int d = idx >> 6, h = idx & 63;
            wg1[d * 65 + h] = W_G1[idx];
            wg2[idx]        = W_G2[m * 4096 + idx];
        }
        __syncthreads();
        int d = t >> 2, i0 = (t & 3) * 16;
        float acc[16];
        #pragma unroll
        for (int k = 0; k < 16; k++) acc[k] = 0.f;
        for (int h = 0; h < 64; h++) {
            float a = wg1[d * 65 + h];
            #pragma unroll
            for (int k = 0; k < 16; k++) acc[k] += a * wg2[h * 64 + i0 + k];
        }
        #pragma unroll
        for (int k = 0; k < 16; k++) g_WG12[m * 4096 + d * 64 + i0 + k] = acc[k];
        return;
    }

    // ---- main k0 body (R10-validated) ----
    float* xt = sm;             // [64 f][132]
    float* wf = sm + 64 * 132;  // [64 f][64 h]
    float* wa = wf + 4096;      // [64]
    int b0 = blockIdx.x * 128;
    int i  = blockIdx.y;

    for (int idx = t; idx < 4096; idx += 256) wf[idx] = W_F1[i * 4096 + idx];
    if (t < 64) wa[t] = W_A[i * 64 + t];
    for (int idx = t; idx < 2048; idx += 256) {
        int b = idx >> 4, f0 = (idx & 15) * 4;
        float4 v = *(const float4*)&x[((b0 + b) * 64 + i) * 64 + f0];
        xt[(f0 + 0) * 132 + b] = v.x;
        xt[(f0 + 1) * 132 + b] = v.y;
        xt[(f0 + 2) * 132 + b] = v.z;
        xt[(f0 + 3) * 132 + b] = v.w;
    }
    __syncthreads();

    int bq = t >> 3, dq = t & 7;
    int bb = bq * 4, d0 = dq * 4, d1 = 32 + dq * 4;
    ull pacc[4][4];
    #pragma unroll
    for (int j = 0; j < 4; j++)
        #pragma unroll
        for (int k = 0; k < 4; k++) pacc[j][k] = 0ull;

    #pragma unroll 4
    for (int f = 0; f < 64; f++) {
        float4 xv = *(float4*)&xt[f * 132 + bb];
        ulonglong2 wA = *(ulonglong2*)&wf[f * 64 + d0];
        ulonglong2 wB = *(ulonglong2*)&wf[f * 64 + d1];
        ull xb[4] = {bcast2(xv.x), bcast2(xv.y), bcast2(xv.z), bcast2(xv.w)};
        #pragma unroll
        for (int j = 0; j < 4; j++) {
            fma2(pacc[j][0], xb[j], wA.x);
            fma2(pacc[j][1], xb[j], wA.y);
            fma2(pacc[j][2], xb[j], wB.x);
            fma2(pacc[j][3], xb[j], wB.y);
        }
    }
    #pragma unroll
    for (int j = 0; j < 4; j++) {
        float2 a0 = unpk(pacc[j][0]), a1 = unpk(pacc[j][1]);
        float2 a2 = unpk(pacc[j][2]), a3 = unpk(pacc[j][3]);
        int base = ((b0 + bb + j) * 64 + i) * 64;
        *(float4*)&g_tempF[base + d0] = make_float4(a0.x * 0.125f, a0.y * 0.125f,
                                                    a1.x * 0.125f, a1.y * 0.125f);
        *(float4*)&g_tempF[base + d1] = make_float4(a2.x * 0.125f, a2.y * 0.125f,
                                                    a3.x * 0.125f, a3.y * 0.125f);
    }

    if (t < 128) {
        int b = t;
        float a = 0.f;
        #pragma unroll 8
        for (int f = 0; f < 64; f++) a = fmaf(xt[f * 132 + b], wa[f], a);
        a = a * 0.125f + B_A[i];
        g_fa[(b0 + b) * 64 + i] = 1.f / (1.f + __expf(-a));
    }
}

// -------------------- ky1: iteration-1 y (s = fa*c0 inline)
__global__ void ky1() {
    int t = threadIdx.x;
    int w = t >> 5, l = t & 31;
    int b = blockIdx.x * 8 + w;
    int r = l >> 4, c = l & 15;
    float sA = g_fa[b * 64 + l] * g_c0[l];
    float sB = g_fa[b * 64 + 32 + l] * g_c0[32 + l];
    const float4* tf = (const float4*)(g_tempF + b * 4096);
    float4 acc = make_float4(0.f, 0.f, 0.f, 0.f);
    #pragma unroll
    for (int k = 0; k < 32; k++) {
        int idx = 2 * k + r;
        float sv = (k < 16) ? __shfl_sync(0xffffffffu, sA, idx)
                            : __shfl_sync(0xffffffffu, sB, idx - 32);
        float4 p = tf[idx * 16 + c];
        acc.x = fmaf(sv, p.x, acc.x);
        acc.y = fmaf(sv, p.y, acc.y);
        acc.z = fmaf(sv, p.z, acc.z);
        acc.w = fmaf(sv, p.w, acc.w);
    }
    acc.x += __shfl_xor_sync(0xffffffffu, acc.x, 16);
    acc.y += __shfl_xor_sync(0xffffffffu, acc.y, 16);
    acc.z += __shfl_xor_sync(0xffffffffu, acc.z, 16);
    acc.w += __shfl_xor_sync(0xffffffffu, acc.w, 16);
    if (r == 0) ((float4*)g_y)[b * 16 + c] = acc;
}

// -------------------- kxm: x_out = y@W_F2+B_F2 ; [LN ; xhat = xn@W_G12+B_G2]
// grid (32, 16), 256 threads; single shared w buffer (W_F2 then W_G12)
template <bool LAST>
__global__ void __launch_bounds__(256, 4) kxm(const float* __restrict__ W_F2,
                    const float* __restrict__ B_F2,
                    const float* __restrict__ B_G2, const float* __restrict__ gamma,
                    const float* __restrict__ beta, float* __restrict__ out) {
    extern __shared__ float sm[];
    float* yt = sm;             // [64 h][132]  (xn_t reuses this)
    float* w  = sm + 64 * 132;  // [64][64]  W_F2[m], later W_G12[m]
    int t  = threadIdx.x;
    int b0 = blockIdx.x * 128;
    int m  = blockIdx.y;

    for (int idx = t; idx < 8192; idx += 256) {
        int b = idx >> 6, h = idx & 63;
        yt[h * 132 + b] = g_y[(b0 + b) * 64 + h];
    }
    for (int idx = t; idx < 4096; idx += 256) w[idx] = W_F2[m * 4096 + idx];
    __syncthreads();

    int bq = t >> 3, dq = t & 7;
    int bb = bq * 4, d0 = dq * 4, d1 = 32 + dq * 4;

    ull pacc[4][4];
    #pragma unroll
    for (int j = 0; j < 4; j++)
        #pragma unroll
        for (int k = 0; k < 4; k++) pacc[j][k] = 0ull;

    #pragma unroll 4
    for (int h = 0; h < 64; h++) {
        float4 yv = *(float4*)&yt[h * 132 + bb];
        ulonglong2 wA = *(ulonglong2*)&w[h * 64 + d0];
        ulonglong2 wB = *(ulonglong2*)&w[h * 64 + d1];
        ull yb[4] = {bcast2(yv.x), bcast2(yv.y), bcast2(yv.z), bcast2(yv.w)};
        #pragma unroll
        for (int j = 0; j < 4; j++) {
            fma2(pacc[j][0], yb[j], wA.x);
            fma2(pacc[j][1], yb[j], wA.y);
            fma2(pacc[j][2], yb[j], wB.x);
            fma2(pacc[j][3], yb[j], wB.y);
        }
    }

    float acc[4][8];
    float4 bfA = *(const float4*)&B_F2[m * 64 + d0];
    float4 bfB = *(const float4*)&B_F2[m * 64 + d1];
    #pragma unroll
    for (int j = 0; j < 4; j++) {
        float2 a0 = unpk(pacc[j][0]), a1 = unpk(pacc[j][1]);
        float2 a2 = unpk(pacc[j][2]), a3 = unpk(pacc[j][3]);
        acc[j][0] = a0.x + bfA.x; acc[j][1] = a0.y + bfA.y;
        acc[j][2] = a1.x + bfA.z; acc[j][3] = a1.y + bfA.w;
        acc[j][4] = a2.x + bfB.x; acc[j][5] = a2.y + bfB.y;
        acc[j][6] = a3.x + bfB.z; acc[j][7] = a3.y + bfB.w;
    }

    if (LAST) {
        #pragma unroll
        for (int j = 0; j < 4; j++) {
            int base = ((b0 + bb + j) * 16 + m) * 64;
            *(float4*)&out[base + d0] = make_float4(acc[j][0], acc[j][1], acc[j][2], acc[j][3]);
            *(float4*)&out[base + d1] = make_float4(acc[j][4], acc[j][5], acc[j][6], acc[j][7]);
        }
        return;
    }

    float4 gA = *(const float4*)&gamma[d0];
    float4 gB = *(const float4*)&gamma[d1];
    float4 eA = *(const float4*)&beta[d0];
    float4 eB = *(const float4*)&beta[d1];
    float gam[8] = {gA.x, gA.y, gA.z, gA.w, gB.x, gB.y, gB.z, gB.w};
    float bet[8] = {eA.x, eA.y, eA.z, eA.w, eB.x, eB.y, eB.z, eB.w};

    __syncthreads();   // all yt and w reads done (yt -> xn_t, w -> W_G12)

    // stage W_G12 into the same w buffer (loads issued early, overlap LN)
    for (int idx = t; idx < 4096; idx += 256) w[idx] = g_WG12[m * 4096 + idx];

    float xn[4][8];
    #pragma unroll
    for (int j = 0; j < 4; j++) {
        float s1 = 0.f, s2 = 0.f;
        #pragma unroll
        for (int k = 0; k < 8; k++) { s1 += acc[j][k]; s2 = fmaf(acc[j][k], acc[j][k], s2); }
        #pragma unroll
        for (int off = 1; off < 8; off <<= 1) {
            s1 += __shfl_xor_sync(0xffffffffu, s1, off);
            s2 += __shfl_xor_sync(0xffffffffu, s2, off);
        }
        float mu   = s1 * (1.f / 64.f);
        float var  = s2 * (1.f / 64.f) - mu * mu;
        float rstd = rsqrtf(var + 1e-5f);
        #pragma unroll
        for (int k = 0; k < 8; k++)
            xn[j][k] = fmaf((acc[j][k] - mu) * rstd, gam[k], bet[k]);
    }
    // store xn transposed [d][b]
    #pragma unroll
    for (int j = 0; j < 4; j++) {
        #pragma unroll
        for (int k = 0; k < 4; k++) {
            yt[(d0 + k) * 132 + bb + j] = xn[j][k];
            yt[(d1 + k) * 132 + bb + j] = xn[j][k + 4];
        }
    }
    __syncthreads();

    ull pacc2[4][4];
    #pragma unroll
    for (int j = 0; j < 4; j++)
        #pragma unroll
        for (int k = 0; k < 4; k++) pacc2[j][k] = 0ull;

    #pragma unroll 4
    for (int d = 0; d < 64; d++) {
        float4 xv = *(float4*)&yt[d * 132 + bb];
        ulonglong2 wA = *(ulonglong2*)&w[d * 64 + d0];
        ulonglong2 wB = *(ulonglong2*)&w[d * 64 + d1];
        ull xb[4] = {bcast2(xv.x), bcast2(xv.y), bcast2(xv.z), bcast2(xv.w)};
        #pragma unroll
        for (int j = 0; j < 4; j++) {
            fma2(pacc2[j][0], xb[j], wA.x);
            fma2(pacc2[j][1], xb[j], wA.y);
            fma2(pacc2[j][2], xb[j], wB.x);
            fma2(pacc2[j][3], xb[j], wB.y);
        }
    }
    float4 bgA = *(const float4*)&B_G2[m * 64 + d0];
    float4 bgB = *(const float4*)&B_G2[m * 64 + d1];
    #pragma unroll
    for (int j = 0; j < 4; j++) {
        float2 a0 = unpk(pacc2[j][0]), a1 = unpk(pacc2[j][1]);
        float2 a2 = unpk(pacc2[j][2]), a3 = unpk(pacc2[j][3]);
        int base = ((b0 + bb + j) * 16 + m) * 64;
        *(float4*)&g_xhat[base + d0] = make_float4(a0.x + bgA.x, a0.y + bgA.y,
                                                   a1.x + bgA.z, a1.y + bgA.w);
        *(float4*)&g_xhat[base + d1] = make_float4(a2.x + bgB.x, a2.y + bgB.y,
                                                   a3.x + bgB.z, a3.y + bgB.w);
    }
}

// -------------------- kBy (R10-validated): consistency + softmax + s (2 i per round),
// then y epilogue. grid 256 (16 b/CTA), 256 threads (16 b x 16 m)
__global__ void __launch_bounds__(256) kBy(const float* __restrict__ x,
                                           const float* __restrict__ W_S,
                                           const float* __restrict__ B_S) {
    __shared__ float xsm[2][16 * 68];
    __shared__ float ws [2][16 * 68];
    __shared__ float bsum_sm[64 * 16];
    __shared__ float bs_sm  [64 * 16];
    __shared__ float bI_sm  [64];
    __shared__ float fasm   [16 * 64];
    __shared__ float s_sm   [16 * 64];
    int t  = threadIdx.x;
    int bl = t >> 4, m = t & 15;
    int b0 = blockIdx.x * 16;
    int b  = b0 + bl;

    ulonglong2 xh2[16];
    const ulonglong2* xp = (const ulonglong2*)(g_xhat + (b * 16 + m) * 64);
    #pragma unroll
    for (int v = 0; v < 16; v++) xh2[v] = xp[v];

    for (int idx = t; idx < 1024; idx += 256) {
        bsum_sm[idx] = g_bsum[idx];
        bs_sm[idx]   = B_S[idx];
        fasm[idx]    = g_fa[(b0 + (idx >> 6)) * 64 + (idx & 63)];
    }
    if (t < 64) bI_sm[t] = g_bI[t];

    int bb2 = t >> 4, f0 = (t & 15) * 4;
    float4 px0 = *(const float4*)&x[((b0 + bb2) * 64 + 0) * 64 + f0];
    float4 pw0 = *(const float4*)&W_S[(0 * 16 + bb2) * 64 + f0];
    float4 px1 = *(const float4*)&x[((b0 + bb2) * 64 + 1) * 64 + f0];
    float4 pw1 = *(const float4*)&W_S[(1 * 16 + bb2) * 64 + f0];

    for (int r = 0; r < 32; r++) {
        int i0 = 2 * r, i1 = 2 * r + 1;
        __syncthreads();
        *(float4*)&xsm[0][bb2 * 68 + f0] = px0;
        *(float4*)&ws [0][bb2 * 68 + f0] = pw0;
        *(float4*)&xsm[1][bb2 * 68 + f0] = px1;
        *(float4*)&ws [1][bb2 * 68 + f0] = pw1;
        __syncthreads();
        if (r < 31) {
            px0 = *(const float4*)&x[((b0 + bb2) * 64 + i0 + 2) * 64 + f0];
            pw0 = *(const float4*)&W_S[((i0 + 2) * 16 + bb2) * 64 + f0];
            px1 = *(const float4*)&x[((b0 + bb2) * 64 + i1 + 2) * 64 + f0];
            pw1 = *(const float4*)&W_S[((i1 + 2) * 16 + bb2) * 64 + f0];
        }

        ull a0A = 0ull, a0B = 0ull, a1A = 0ull, a1B = 0ull;
        #pragma unroll
        for (int fq = 0; fq < 16; fq++) {
            ulonglong2 xv0 = *(ulonglong2*)&xsm[0][bl * 68 + fq * 4];
            ulonglong2 wv0 = *(ulonglong2*)&ws [0][m  * 68 + fq * 4];
            ulonglong2 xv1 = *(ulonglong2*)&xsm[1][bl * 68 + fq * 4];
            ulonglong2 wv1 = *(ulonglong2*)&ws [1][m  * 68 + fq * 4];
            fma2(a0A, mul2(xv0.x, wv0.x), xh2[fq].x);
            fma2(a0B, mul2(xv0.y, wv0.y), xh2[fq].y);
            fma2(a1A, mul2(xv1.x, wv1.x), xh2[fq].x);
            fma2(a1B, mul2(xv1.y, wv1.y), xh2[fq].y);
        }
        float2 r0a = unpk(a0A), r0b = unpk(a0B);
        float2 r1a = unpk(a1A), r1b = unpk(a1B);
        float acc0 = bs_sm[i0 * 16 + m] + ((r0a.x + r0a.y) + (r0b.x + r0b.y));
        float acc1 = bs_sm[i1 * 16 + m] + ((r1a.x + r1a.y) + (r1b.x + r1b.y));

        // interleaved 16-lane softmax chains (ILP=2)
        float mx0 = acc0, mx1 = acc1;
        #pragma unroll
        for (int off = 1; off < 16; off <<= 1) {
            mx0 = fmaxf(mx0, __shfl_xor_sync(0xffffffffu, mx0, off));
            mx1 = fmaxf(mx1, __shfl_xor_sync(0xffffffffu, mx1, off));
        }
        float e0 = __expf(acc0 - mx0);
        float e1 = __expf(acc1 - mx1);
        float num0 = e0 * bsum_sm[i0 * 16 + m], den0 = e0;
        float num1 = e1 * bsum_sm[i1 * 16 + m], den1 = e1;
        #pragma unroll
        for (int off = 1; off < 16; off <<= 1) {
            num0 += __shfl_xor_sync(0xffffffffu, num0, off);
            den0 += __shfl_xor_sync(0xffffffffu, den0, off);
            num1 += __shfl_xor_sync(0xffffffffu, num1, off);
            den1 += __shfl_xor_sync(0xffffffffu, den1, off);
        }
        if (m == 0) {
            s_sm[bl * 64 + i0] = fasm[bl * 64 + i0] * (num0 / den0 - bI_sm[i0]);
            s_sm[bl * 64 + i1] = fasm[bl * 64 + i1] * (num1 / den1 - bI_sm[i1]);
        }
    }

    // ---- epilogue: y[b, 4m..4m+3] = sum_i s[b,i] * tempF[b,i,4m..4m+3]
    __syncthreads();
    const float4* tfb = (const float4*)(g_tempF + b * 4096) + m;
    float4 yacc = make_float4(0.f, 0.f, 0.f, 0.f);
    #pragma unroll 16
    for (int i = 0; i < 64; i++) {
        float sv = s_sm[bl * 64 + i];
        float4 p = tfb[i * 16];
        yacc.x = fmaf(sv, p.x, yacc.x);
        yacc.y = fmaf(sv, p.y, yacc.y);
        yacc.z = fmaf(sv, p.z, yacc.z);
        yacc.w = fmaf(sv, p.w, yacc.w);
    }
    ((float4*)g_y)[b * 16 + m] = yacc;
}

// ---------------------------------------------------------------- launcher
extern "C" void kernel_launch(void* const* d_in, const int* in_sizes, int n_in,
                              void* d_out, int out_size) {
    const float* x    = (const float*)d_in[0];
    const float* W_A  = (const float*)d_in[1];
    const float* B_A  = (const float*)d_in[2];
    const float* W_F1 = (const float*)d_in[3];
    const float* W_F2 = (const float*)d_in[4];
    const float* B_F2 = (const float*)d_in[5];
    const float* W_G1 = (const float*)d_in[6];
    const float* W_G2 = (const float*)d_in[7];
    const float* B_G2 = (const float*)d_in[8];
    const float* gam  = (const float*)d_in[9];
    const float* bet  = (const float*)d_in[10];
    const float* W_S  = (const float*)d_in[11];
    const float* B_S  = (const float*)d_in[12];
    const float* bu   = (const float*)d_in[13];
    const float* bg   = (const float*)d_in[14];
    float* out = (float*)d_out;

    const int K0_SMEM  = (64 * 132 + 4096 + 64) * 4;     // 50432 B
    const int KXM_SMEM = (64 * 132 + 4096) * 4;          // 50176 B
    cudaFuncSetAttribute(k0, cudaFuncAttributeMaxDynamicSharedMemorySize, K0_SMEM);
    cudaFuncSetAttribute(kxm<false>, cudaFuncAttributeMaxDynamicSharedMemorySize, KXM_SMEM);
    cudaFuncSetAttribute(kxm<true>,  cudaFuncAttributeMaxDynamicSharedMemorySize, KXM_SMEM);

    // k0 + folded prep plane (blockIdx.y == 64)
    k0<<<dim3(32, 65), 256, K0_SMEM>>>(x, W_F1, W_A, B_A, W_G1, W_G2, bu, bg);

    // iteration 1
    ky1<<<512, 256>>>();
    kxm<false><<<dim3(32, 16), 256, KXM_SMEM>>>(W_F2, B_F2, B_G2, gam, bet, nullptr);
    // iteration 2
    kBy<<<256, 256>>>(x, W_S, B_S);
    kxm<false><<<dim3(32, 16), 256, KXM_SMEM>>>(W_F2, B_F2, B_G2, gam, bet, nullptr);
    // iteration 3
    kBy<<<256, 256>>>(x, W_S, B_S);
    kxm<true><<<dim3(32, 16), 256, KXM_SMEM>>>(W_F2, B_F2, B_G2, gam, bet, out);
}